// round 1
// baseline (speedup 1.0000x reference)
#include <cuda_runtime.h>
#include <math.h>

#define NEGF (-1e30f)
#define MAXB 16
#define NCH  32   // chunks for denominator scan

// Scratch (static device arrays; no allocations allowed)
__device__ float g_num[MAXB];                       // numerator logZ per batch
__device__ float g_LP[MAXB * NCH * 8 * 8];          // [b][c][j][i] log chunk matrices

__device__ __forceinline__ float lae(float a, float b) {
    // logaddexp, safe for both args == -1e30 (d=0 -> m+log2)
    float m = fmaxf(a, b);
    float d = fminf(a, b) - m;       // <= 0
    return m + __logf(1.0f + __expf(d));
}

// One numerator step (slot-specialized so prefetch regs stay in registers)
#define NUM_STEP(T_, EME, EMX) do {                                          \
    float pe = __shfl_up_sync(0xffffffffu, a_e, 1);                          \
    float px = __shfl_up_sync(0xffffffffu, a_x, 1);                          \
    int buf_ = (T_) & 1;                                                     \
    if (lane == 31) { sm_be[buf_][warp] = a_e; sm_bx[buf_][warp] = a_x; }    \
    __syncthreads();                                                         \
    if (lane == 0) {                                                         \
        if (warp > 0) { pe = sm_be[buf_][warp-1]; px = sm_bx[buf_][warp-1]; }\
        else          { pe = NEGF; px = NEGF; }                              \
    }                                                                        \
    float ne_ = (EME) + lae(pe + t_ee, px + t_xe);                           \
    float nx_ = (EMX) + lae(a_e + t_ex, a_x + t_xx);                         \
    int tp_ = (T_) + 4; tp_ = (tp_ > len - 1) ? (len - 1) : tp_;             \
    (EME) = __ldg(emb + tp_ * 8 + es);                                       \
    (EMX) = __ldg(emb + tp_ * 8 + xs);                                       \
    a_e = ne_; a_x = nx_;                                                    \
} while (0)

extern "C" __global__ void __launch_bounds__(256, 1)
ctccrf_main(const float* __restrict__ em,      // (B,T,8)
            const float* __restrict__ trans,   // (8,8)
            const float* __restrict__ bos,     // (8)
            const float* __restrict__ eos,     // (8)
            const int*   __restrict__ lengths, // (B)
            const int*   __restrict__ targets, // (B,L)
            const int*   __restrict__ tlens,   // (B)
            int B, int T, int L)
{
    if ((int)blockIdx.x < B) {
        // ---------------- Numerator: one CTA per batch, lane u = thread ----------------
        const int b    = blockIdx.x;
        const int u    = threadIdx.x;          // 0..L-1
        const int lane = u & 31;
        const int warp = u >> 5;
        __shared__ float sm_be[2][32], sm_bx[2][32];

        const int len = lengths[b];
        const int tg  = __ldg(targets + b * L + u);
        const int es  = tg;
        const int xs  = tg + 4;
        const int tgp = (u == 0) ? tg : __ldg(targets + b * L + u - 1);
        const float t_ee = __ldg(trans + tgp * 8 + es);
        const float t_xe = __ldg(trans + (tgp + 4) * 8 + es);
        const float t_ex = __ldg(trans + es * 8 + xs);
        const float t_xx = __ldg(trans + xs * 8 + xs);

        const float* emb = em + (size_t)b * T * 8;
        float a_e = (u == 0) ? (__ldg(bos + es) + __ldg(emb + es)) : NEGF;
        float a_x = NEGF;

        // prefetch em for t = 1..4 (clamped)
        float eme0, eme1, eme2, eme3, emx0, emx1, emx2, emx3;
        {
            int t1c = min(1, len - 1), t2c = min(2, len - 1);
            int t3c = min(3, len - 1), t4c = min(4, len - 1);
            eme0 = __ldg(emb + t1c * 8 + es); emx0 = __ldg(emb + t1c * 8 + xs);
            eme1 = __ldg(emb + t2c * 8 + es); emx1 = __ldg(emb + t2c * 8 + xs);
            eme2 = __ldg(emb + t3c * 8 + es); emx2 = __ldg(emb + t3c * 8 + xs);
            eme3 = __ldg(emb + t4c * 8 + es); emx3 = __ldg(emb + t4c * 8 + xs);
        }

        int t = 1;
        for (; t + 3 < len; t += 4) {
            NUM_STEP(t    , eme0, emx0);
            NUM_STEP(t + 1, eme1, emx1);
            NUM_STEP(t + 2, eme2, emx2);
            NUM_STEP(t + 3, eme3, emx3);
        }
        // remainder (uniform branches: len identical across block)
        if (t < len) { NUM_STEP(t, eme0, emx0); t++; }
        if (t < len) { NUM_STEP(t, eme1, emx1); t++; }
        if (t < len) { NUM_STEP(t, eme2, emx2); t++; }

        const int tl = tlens[b];
        if (u == tl - 1) {
            float fe = a_e + __ldg(eos + es);
            float fx = a_x + __ldg(eos + xs);
            g_num[b] = lae(fe, fx);
        }
    } else {
        // ------------- Denominator Phase A: chunked 8x8 linear-space scan -------------
        const int db = blockIdx.x - B;          // batch
        if (db >= B) return;
        const int c = threadIdx.x >> 3;         // chunk 0..31
        const int i = threadIdx.x & 7;          // row of chunk matrix
        const int len = lengths[db];
        const int C = (T - 1 + NCH - 1) / NCH;  // steps per chunk

        float E[64];
        #pragma unroll
        for (int k = 0; k < 64; ++k) E[k] = __expf(__ldg(trans + k));

        float r[8];
        #pragma unroll
        for (int j = 0; j < 8; ++j) r[j] = (j == i) ? 1.0f : 0.0f;
        float off = 0.0f;

        const int t0 = 1 + c * C;
        const int t1 = min(t0 + C, len);
        const float* emb = em + (size_t)db * T * 8;

        for (int t = t0; t < t1; ++t) {
            float4 lo = __ldg((const float4*)(emb + t * 8));
            float4 hi = __ldg((const float4*)(emb + t * 8 + 4));
            float Em[8];
            Em[0] = __expf(lo.x); Em[1] = __expf(lo.y);
            Em[2] = __expf(lo.z); Em[3] = __expf(lo.w);
            Em[4] = __expf(hi.x); Em[5] = __expf(hi.y);
            Em[6] = __expf(hi.z); Em[7] = __expf(hi.w);

            float s[8];
            #pragma unroll
            for (int j = 0; j < 8; ++j) {
                float acc = r[0] * E[0 * 8 + j];
                #pragma unroll
                for (int k = 1; k < 8; ++k) acc = fmaf(r[k], E[k * 8 + j], acc);
                s[j] = acc * Em[j];
            }
            #pragma unroll
            for (int j = 0; j < 8; ++j) r[j] = s[j];

            if (((t - t0) & 3) == 3) {
                float m = r[0];
                #pragma unroll
                for (int j = 1; j < 8; ++j) m = fmaxf(m, r[j]);
                float inv = __fdividef(1.0f, m);
                off += __logf(m);
                #pragma unroll
                for (int j = 0; j < 8; ++j) r[j] *= inv;
            }
        }

        #pragma unroll
        for (int j = 0; j < 8; ++j) {
            float lv = (r[j] > 0.0f) ? (__logf(r[j]) + off) : NEGF;
            g_LP[(((db * NCH) + c) * 8 + j) * 8 + i] = lv;
        }
    }
}

extern "C" __global__ void __launch_bounds__(128, 1)
ctccrf_finish(const float* __restrict__ em,
              const float* __restrict__ bos,
              const float* __restrict__ eos,
              float* __restrict__ out,
              int B, int T)
{
    __shared__ float sa[128];
    __shared__ float sden[MAXB];
    const int tid = threadIdx.x;
    const int b = tid >> 3, j = tid & 7;
    const bool active = (b < B);

    float alpha = 0.0f;
    if (active) alpha = __ldg(bos + j) + __ldg(em + (size_t)b * T * 8 + j);

    for (int c = 0; c < NCH; ++c) {
        sa[tid] = alpha;
        __syncthreads();
        if (active) {
            const float* lp = g_LP + (((b * NCH) + c) * 8 + j) * 8;
            float v[8], m = -3.0e38f;
            #pragma unroll
            for (int i = 0; i < 8; ++i) {
                v[i] = sa[b * 8 + i] + __ldg(lp + i);
                m = fmaxf(m, v[i]);
            }
            float ssum = 0.0f;
            #pragma unroll
            for (int i = 0; i < 8; ++i) ssum += __expf(v[i] - m);
            alpha = m + __logf(ssum);
        }
        __syncthreads();
    }

    sa[tid] = active ? (alpha + __ldg(eos + j)) : NEGF;
    __syncthreads();
    if (active && j == 0) {
        float m = sa[b * 8];
        #pragma unroll
        for (int i = 1; i < 8; ++i) m = fmaxf(m, sa[b * 8 + i]);
        float ssum = 0.0f;
        #pragma unroll
        for (int i = 0; i < 8; ++i) ssum += __expf(sa[b * 8 + i] - m);
        sden[b] = m + __logf(ssum);
    }
    __syncthreads();
    if (tid == 0) {
        float acc = 0.0f;
        for (int bb = 0; bb < B; ++bb) acc += sden[bb] - g_num[bb];
        out[0] = acc / (float)B;
    }
}

extern "C" void kernel_launch(void* const* d_in, const int* in_sizes, int n_in,
                              void* d_out, int out_size)
{
    const float* em     = (const float*)d_in[0];  // (B,T,8)
    const float* trans  = (const float*)d_in[1];  // (8,8)
    const float* bos    = (const float*)d_in[2];  // (8)
    const float* eos    = (const float*)d_in[3];  // (8)
    const int*   lens   = (const int*)  d_in[4];  // (B)
    const int*   tgts   = (const int*)  d_in[5];  // (B,L)
    const int*   tlens  = (const int*)  d_in[6];  // (B)
    float* out = (float*)d_out;

    const int B = in_sizes[4];                 // 16
    const int T = in_sizes[0] / (B * 8);       // 2048
    const int L = in_sizes[5] / B;             // 256

    // Blocks [0,B): numerator (L threads of work, blockDim = L).
    // Blocks [B,2B): denominator phase A (NCH chunks x 8 rows = 256 threads).
    ctccrf_main<<<2 * B, 256>>>(em, trans, bos, eos, lens, tgts, tlens, B, T, L);
    ctccrf_finish<<<1, 128>>>(em, bos, eos, out, B, T);
}